// round 14
// baseline (speedup 1.0000x reference)
#include <cuda_runtime.h>

namespace {
constexpr int W      = 512;
constexpr int H      = 512;
constexpr int PLANES = 16 * 3;         // 48
constexpr int NBLK   = 296;            // 148 SMs x occ 2, exactly one wave
constexpr int NT     = 256;
constexpr int RB     = 528;            // row buffer floats (stride mult of 16B)
constexpr int MAXRI  = 96;             // max riter = 86 + 10; 96 = 8 * 12
constexpr float C1c  = 1e-4f;
constexpr float C2c  = 9e-4f;
}

__device__ float g_partials[NBLK];
__device__ int   g_count = 0;

// ---------------- packed f32x2 helpers (sm_103a) ----------------
using u64 = unsigned long long;

static __device__ __forceinline__ u64 pk2(float lo, float hi) {
    u64 r; asm("mov.b64 %0, {%1, %2};" : "=l"(r) : "f"(lo), "f"(hi)); return r;
}
static __device__ __forceinline__ u64 pkf2(float2 v) { return pk2(v.x, v.y); }
static __device__ __forceinline__ void upk2(u64 v, float& lo, float& hi) {
    asm("mov.b64 {%0, %1}, %2;" : "=f"(lo), "=f"(hi) : "l"(v));
}
static __device__ __forceinline__ u64 fma2(u64 a, u64 b, u64 c) {
    u64 d; asm("fma.rn.f32x2 %0, %1, %2, %3;" : "=l"(d) : "l"(a), "l"(b), "l"(c)); return d;
}
static __device__ __forceinline__ u64 add2(u64 a, u64 b) {
    u64 d; asm("add.rn.f32x2 %0, %1, %2;" : "=l"(d) : "l"(a), "l"(b)); return d;
}
static __device__ __forceinline__ u64 mul2(u64 a, u64 b) {
    u64 d; asm("mul.rn.f32x2 %0, %1, %2;" : "=l"(d) : "l"(a), "l"(b)); return d;
}
// (a.hi, b.lo) as a packed pair
static __device__ __forceinline__ u64 hilo(u64 a, u64 b) {
    float al, ah, bl, bh; upk2(a, al, ah); upk2(b, bl, bh); return pk2(ah, bl);
}

// One 11-tap weighted chain from a 12-slot ring. Output row R has slot base
// kB = (R+12)%12-aligned: taps j -> slot (kB + j) % 12, center j=5.
// Here kB = slot of row R = (k0 + 2 + off) for off in {0,1}.
template <int KB>
static __device__ __forceinline__ u64 chain(const u64 r[12], const u64 Wv[6]) {
    u64 v = mul2(Wv[5], r[(KB + 5) % 12]);
#pragma unroll
    for (int j = 0; j < 5; ++j)
        v = fma2(Wv[j], add2(r[(KB + j) % 12], r[(KB + 10 - j) % 12]), v);
    return v;
}

// h[0]=mu_x, h[1]=mu_y, h[2]=blur(x^2+y^2), h[3]=blur(xy)
static __device__ __forceinline__ float ssim2(const u64 h[4], u64 C1_2, u64 C2_2,
                                              u64 EPS2, u64 NEG1, u64 TWO) {
    const u64 musq = fma2(h[0], h[0], mul2(h[1], h[1]));  // mu_x^2 + mu_y^2
    const u64 mxy  = mul2(h[0], h[1]);
    const u64 ssum = fma2(musq, NEG1, h[2]);              // sigma_x^2 + sigma_y^2
    const u64 sxy  = fma2(mxy,  NEG1, h[3]);
    const u64 num = mul2(fma2(mxy, TWO, C1_2), fma2(sxy, TWO, C2_2));
    const u64 den = add2(mul2(add2(musq, C1_2), add2(ssum, C2_2)), EPS2);
    float n0, n1, d0, d1;
    upk2(num, n0, n1);
    upk2(den, d0, d1);
    return __fdividef(n0, d0) + __fdividef(n1, d1);
}

__global__ __launch_bounds__(NT, 2)
void ssim_main(const float* __restrict__ X, const float* __restrict__ Y,
               float* __restrict__ out) {
    // Double-buffered 2-row exchange: [phase-buffer][row-in-phase][quantity][RB]
    __shared__ __align__(16) float sq[2][2][4][RB];
    __shared__ float wsum[NT / 32];
    __shared__ int amLast;

    const int t = threadIdx.x;              // vertical role: cols (2t, 2t+1)
    const int b = blockIdx.x;               // 0..295

    // ---- Balanced tiling: planes 0-7 have 7 chunks, planes 8-47 have 6 ----
    int plane, r0, ch;
    if (b < 56) {
        plane = b / 7;
        const int c = b % 7;                 // sizes 74,74,74,74,72,72,72
        ch = (c < 4) ? 74 : 72;
        r0 = (c < 4) ? 74 * c : 296 + 72 * (c - 4);
    } else {
        const int bb = b - 56;
        plane = 8 + bb / 6;
        const int c = bb % 6;                // sizes 86,86,86,86,84,84
        ch = (c < 4) ? 86 : 84;
        r0 = (c < 4) ? 86 * c : 344 + 84 * (c - 4);
    }
    const int riter = ch + 10;

    const int hrow = t >> 7;                // horizontal role: row-in-phase
    const int u    = t & 127;               // horizontal role: cols 4u..4u+3

    const float2* __restrict__ X2 =
        reinterpret_cast<const float2*>(X + (size_t)plane * W * H);
    const float2* __restrict__ Y2 =
        reinterpret_cast<const float2*>(Y + (size_t)plane * W * H);

    // Zero pads once (stores below only touch idx [6 .. 517]).
    if (t < 6) {
#pragma unroll
        for (int pb = 0; pb < 2; ++pb)
#pragma unroll
            for (int r = 0; r < 2; ++r)
#pragma unroll
                for (int q = 0; q < 4; ++q) sq[pb][r][q][t] = 0.f;
    }
    if (t < 10) {
#pragma unroll
        for (int pb = 0; pb < 2; ++pb)
#pragma unroll
            for (int r = 0; r < 2; ++r)
#pragma unroll
                for (int q = 0; q < 4; ++q) sq[pb][r][q][518 + t] = 0.f;
    }

    const float Gw[6] = {0.00102838f, 0.00759875f, 0.03600077f,
                         0.10936070f, 0.21300554f, 0.26601172f};
    u64 Wv[6];
#pragma unroll
    for (int i = 0; i < 6; ++i) Wv[i] = pk2(Gw[i], Gw[i]);
    const u64 NEG1 = pk2(-1.f, -1.f);
    const u64 TWO  = pk2(2.f, 2.f);
    const u64 C1_2 = pk2(C1c, C1c);
    const u64 C2_2 = pk2(C2c, C2c);
    const u64 EPS2 = pk2(1e-8f, 1e-8f);

    // 12-slot register ring of raw x,y (packed column pair). Row r -> slot r%12.
    u64 xr[12], yr[12];

    // Prefetch rows 0,1 (image rows r0-5, r0-4).
    float2 p0x, p0y, p1x, p1y;
    {
        const int ra = r0 - 5, rb = r0 - 4;
        const bool oa = ((unsigned)ra < (unsigned)H);
        const bool ob = ((unsigned)rb < (unsigned)H);
        p0x = oa ? X2[(size_t)ra * (W / 2) + t] : make_float2(0.f, 0.f);
        p0y = oa ? Y2[(size_t)ra * (W / 2) + t] : make_float2(0.f, 0.f);
        p1x = ob ? X2[(size_t)rb * (W / 2) + t] : make_float2(0.f, 0.f);
        p1y = ob ? Y2[(size_t)rb * (W / 2) + t] : make_float2(0.f, 0.f);
    }

    float acc = 0.f;

    // Inner unroll of 6 phases (12 rows) -- ring period. Slots compile-time.
#pragma unroll 1
    for (int outer = 0; outer < MAXRI; outer += 12) {
#pragma unroll
        for (int ph = 0; ph < 6; ++ph) {
            const int rr = outer + 2 * ph;          // even; rows rr, rr+1
            if (rr < riter) {
                const int k0 = 2 * ph;              // slot of row rr
                const int k1 = 2 * ph + 1;          // slot of row rr+1

                // Slots k0,k1 hold rows rr-12, rr-11 -- needed by no vert.
                xr[k0] = pkf2(p0x); yr[k0] = pkf2(p0y);
                xr[k1] = pkf2(p1x); yr[k1] = pkf2(p1y);

                // Prefetch rows rr+2, rr+3 at phase top (full-phase overlap).
                {
                    const int ra = r0 - 5 + rr + 2, rb = ra + 1;
                    const bool oa = (rr + 2 < riter) && ((unsigned)ra < (unsigned)H);
                    const bool ob = (rr + 3 < riter) && ((unsigned)rb < (unsigned)H);
                    p0x = oa ? X2[(size_t)ra * (W / 2) + t] : make_float2(0.f, 0.f);
                    p0y = oa ? Y2[(size_t)ra * (W / 2) + t] : make_float2(0.f, 0.f);
                    p1x = ob ? X2[(size_t)rb * (W / 2) + t] : make_float2(0.f, 0.f);
                    p1y = ob ? Y2[(size_t)rb * (W / 2) + t] : make_float2(0.f, 0.f);
                }

                if (rr >= 10) {
                    const int pb = (rr >> 1) & 1;   // phase buffer
                    // Out rows R=rr-10 (slot base k0+2), R+1 (slot base k0+3).
                    // All 12 slots are tap rows (rr-10 .. rr+1).
                    u64 v0[4], v1[4];

                    // ---- x,y vertical chains (ring direct) ----
                    v0[0] = chain<0 + 2>(xr, Wv);   // KB = k0+2 with k0=2ph:
                    v0[1] = chain<0 + 2>(yr, Wv);   // handled below per-ph
                    // (template arg must be compile-time: specialize via k0)
                    // -- replaced below; see dispatch.
                    (void)v0; (void)v1;

                    // Dispatch on compile-time k0 (ph is unrolled).
                    u64 w[12];
#pragma unroll
                    for (int s = 0; s < 12; ++s)
                        w[s] = fma2(xr[s], xr[s], mul2(yr[s], yr[s]));

                    switch (ph) {   // resolved at compile time under unroll
#define PHASE_CASE(PH)                                                        \
                    case PH: {                                                \
                        constexpr int KB0 = (2 * PH + 2) % 12;                \
                        constexpr int KB1 = (2 * PH + 3) % 12;                \
                        v0[2] = chain<KB0>(w, Wv);                            \
                        v1[2] = chain<KB1>(w, Wv);                            \
                        _Pragma("unroll")                                     \
                        for (int s = 0; s < 12; ++s)                          \
                            w[s] = mul2(xr[s], yr[s]);                        \
                        v0[3] = chain<KB0>(w, Wv);                            \
                        v1[3] = chain<KB1>(w, Wv);                            \
                        v0[0] = chain<KB0>(xr, Wv);                           \
                        v0[1] = chain<KB0>(yr, Wv);                           \
                        v1[0] = chain<KB1>(xr, Wv);                           \
                        v1[1] = chain<KB1>(yr, Wv);                           \
                    } break;
                    PHASE_CASE(0) PHASE_CASE(1) PHASE_CASE(2)
                    PHASE_CASE(3) PHASE_CASE(4) PHASE_CASE(5)
#undef PHASE_CASE
                    }

                    // ---- Exchange: aligned STS.64 (idx 6+2t is even) ----
#pragma unroll
                    for (int q = 0; q < 4; ++q) {
                        *reinterpret_cast<u64*>(&sq[pb][0][q][6 + 2 * t]) = v0[q];
                        *reinterpret_cast<u64*>(&sq[pb][1][q][6 + 2 * t]) = v1[q];
                    }
                    __syncthreads();     // one barrier per 2-row phase

                    // ---- Horizontal: 4 cols of one row per thread ----
                    u64 hA[4], hB[4];    // pairs m=0 (cols 4u,4u+1), m=1
#pragma unroll
                    for (int q = 0; q < 4; ++q) {
                        const float4* P =
                            reinterpret_cast<const float4*>(&sq[pb][hrow][q][4 * u]);
                        const float4 a = P[0], bq = P[1], cq = P[2], d = P[3];
                        // U_j = cols (4u-6+2j, 4u-5+2j), j=0..7
                        const u64 U0 = pk2(a.x, a.y),  U1 = pk2(a.z, a.w);
                        const u64 U2 = pk2(bq.x, bq.y), U3 = pk2(bq.z, bq.w);
                        const u64 U4 = pk2(cq.x, cq.y), U5 = pk2(cq.z, cq.w);
                        const u64 U6 = pk2(d.x, d.y),  U7 = pk2(d.z, d.w);
                        const u64 A2 = add2(U2, U3), A3 = add2(U3, U4), A4 = add2(U4, U5);
                        const u64 B1 = add2(U1, U4), B2 = add2(U2, U5), B3 = add2(U3, U6);
                        const u64 Cg0 = add2(U0, U5), Cg1 = add2(U1, U6), Cg2 = add2(U2, U7);
                        // m = 0
                        u64 h = mul2(Wv[5], U3);
                        h = fma2(Wv[3], add2(U2, U4), h);
                        h = fma2(Wv[1], add2(U1, U5), h);
                        h = fma2(Wv[4], hilo(A2, A3), h);
                        h = fma2(Wv[2], hilo(B1, B2), h);
                        h = fma2(Wv[0], hilo(Cg0, Cg1), h);
                        hA[q] = h;
                        // m = 1
                        u64 g = mul2(Wv[5], U4);
                        g = fma2(Wv[3], add2(U3, U5), g);
                        g = fma2(Wv[1], add2(U2, U6), g);
                        g = fma2(Wv[4], hilo(A3, A4), g);
                        g = fma2(Wv[2], hilo(B2, B3), g);
                        g = fma2(Wv[0], hilo(Cg1, Cg2), g);
                        hB[q] = g;
                    }

                    acc += ssim2(hA, C1_2, C2_2, EPS2, NEG1, TWO);
                    acc += ssim2(hB, C1_2, C2_2, EPS2, NEG1, TWO);
                    // No second barrier: double-buffered across phases.
                }
            }
        }
    }

    // ---- Deterministic block reduction ----
#pragma unroll
    for (int off = 16; off > 0; off >>= 1)
        acc += __shfl_down_sync(0xffffffffu, acc, off);
    const int lane = t & 31, wid = t >> 5;
    if (lane == 0) wsum[wid] = acc;
    __syncthreads();
    if (wid == 0) {
        float v = (lane < NT / 32) ? wsum[lane] : 0.f;
#pragma unroll
        for (int off = 4; off > 0; off >>= 1)
            v += __shfl_down_sync(0xffffffffu, v, off);
        if (lane == 0) g_partials[b] = v;
    }

    // ---- Fused finalize: last block reduces all partials ----
    if (t == 0) {
        __threadfence();
        const int prev = atomicAdd(&g_count, 1);
        amLast = (prev == NBLK - 1);
    }
    __syncthreads();
    if (amLast) {
        float s = (t < NBLK) ? g_partials[t] : 0.f;
        if (t + 256 < NBLK) s += g_partials[t + 256];
#pragma unroll
        for (int off = 16; off > 0; off >>= 1)
            s += __shfl_down_sync(0xffffffffu, s, off);
        if (lane == 0) wsum[wid] = s;
        __syncthreads();
        if (wid == 0) {
            float v = (lane < NT / 32) ? wsum[lane] : 0.f;
#pragma unroll
            for (int off = 4; off > 0; off >>= 1)
                v += __shfl_down_sync(0xffffffffu, v, off);
            if (lane == 0) {
                constexpr float invN = 1.0f / (float)((size_t)PLANES * W * H);
                out[0] = 1.0f - v * invN;
                g_count = 0;        // reset for next graph replay
            }
        }
    }
}

extern "C" void kernel_launch(void* const* d_in, const int* in_sizes, int n_in,
                              void* d_out, int out_size) {
    const float* X = (const float*)d_in[0];
    const float* Y = (const float*)d_in[1];
    float* out = (float*)d_out;

    ssim_main<<<NBLK, NT>>>(X, Y, out);   // 296 blocks = 148 SMs x occ 2
}

// round 15
// speedup vs baseline: 1.0087x; 1.0087x over previous
#include <cuda_runtime.h>

namespace {
constexpr int W      = 512;
constexpr int H      = 512;
constexpr int PLANES = 16 * 3;         // 48
constexpr int NBLK   = 296;            // 148 SMs x occ 2, exactly one wave
constexpr int NT     = 256;
constexpr int RB     = 528;            // row buffer floats (stride mult of 16B)
constexpr int MAXRI  = 96;             // max riter = 86 + 10; 96 = 8 * 12
constexpr int SMEM_BYTES = 4 * 2 * 4 * RB * 4;   // 4 buffers x 2 rows x 4 q
constexpr float C1c  = 1e-4f;
constexpr float C2c  = 9e-4f;
}

__device__ float g_partials[NBLK];
__device__ int   g_count = 0;

// ---------------- packed f32x2 helpers (sm_103a) ----------------
using u64 = unsigned long long;

static __device__ __forceinline__ u64 pk2(float lo, float hi) {
    u64 r; asm("mov.b64 %0, {%1, %2};" : "=l"(r) : "f"(lo), "f"(hi)); return r;
}
static __device__ __forceinline__ u64 pkf2(float2 v) { return pk2(v.x, v.y); }
static __device__ __forceinline__ void upk2(u64 v, float& lo, float& hi) {
    asm("mov.b64 {%0, %1}, %2;" : "=f"(lo), "=f"(hi) : "l"(v));
}
static __device__ __forceinline__ u64 fma2(u64 a, u64 b, u64 c) {
    u64 d; asm("fma.rn.f32x2 %0, %1, %2, %3;" : "=l"(d) : "l"(a), "l"(b), "l"(c)); return d;
}
static __device__ __forceinline__ u64 add2(u64 a, u64 b) {
    u64 d; asm("add.rn.f32x2 %0, %1, %2;" : "=l"(d) : "l"(a), "l"(b)); return d;
}
static __device__ __forceinline__ u64 mul2(u64 a, u64 b) {
    u64 d; asm("mul.rn.f32x2 %0, %1, %2;" : "=l"(d) : "l"(a), "l"(b)); return d;
}
// (a.hi, b.lo) as a packed pair
static __device__ __forceinline__ u64 hilo(u64 a, u64 b) {
    float al, ah, bl, bh; upk2(a, al, ah); upk2(b, bl, bh); return pk2(ah, bl);
}

// Vertical 11-tap blur of x, y, p = x^2+y^2, q = x*y from a 12-slot ring.
// (R10 fused form — best measured.)
static __device__ __forceinline__ void vert(const u64 xr[12], const u64 yr[12],
                                            int kk, const u64 Wv[6], u64 v[4]) {
    const int sC = (kk + 7) % 12;        // row offset 5 (center)
    const u64 xc = xr[sC], yc = yr[sC];
    v[0] = mul2(Wv[5], xc);
    v[1] = mul2(Wv[5], yc);
    v[2] = mul2(Wv[5], fma2(xc, xc, mul2(yc, yc)));
    v[3] = mul2(Wv[5], mul2(xc, yc));
#pragma unroll
    for (int j = 0; j < 5; ++j) {
        const int sA = (kk + 2 + j) % 12;    // row offset j
        const int sB = (kk + 12 - j) % 12;   // row offset 10-j
        const u64 xa = xr[sA], xb = xr[sB];
        const u64 ya = yr[sA], yb = yr[sB];
        v[0] = fma2(Wv[j], add2(xa, xb), v[0]);
        v[1] = fma2(Wv[j], add2(ya, yb), v[1]);
        const u64 pa = fma2(xa, xa, mul2(ya, ya));
        const u64 pb = fma2(xb, xb, mul2(yb, yb));
        v[2] = fma2(Wv[j], add2(pa, pb), v[2]);
        v[3] = fma2(Wv[j], fma2(xa, ya, mul2(xb, yb)), v[3]);
    }
}

// h[0]=mu_x, h[1]=mu_y, h[2]=blur(x^2+y^2), h[3]=blur(xy)
static __device__ __forceinline__ float ssim2(const u64 h[4], u64 C1_2, u64 C2_2,
                                              u64 EPS2, u64 NEG1, u64 TWO) {
    const u64 musq = fma2(h[0], h[0], mul2(h[1], h[1]));  // mu_x^2 + mu_y^2
    const u64 mxy  = mul2(h[0], h[1]);
    const u64 ssum = fma2(musq, NEG1, h[2]);              // sigma_x^2 + sigma_y^2
    const u64 sxy  = fma2(mxy,  NEG1, h[3]);
    const u64 num = mul2(fma2(mxy, TWO, C1_2), fma2(sxy, TWO, C2_2));
    const u64 den = add2(mul2(add2(musq, C1_2), add2(ssum, C2_2)), EPS2);
    float n0, n1, d0, d1;
    upk2(num, n0, n1);
    upk2(den, d0, d1);
    return __fdividef(n0, d0) + __fdividef(n1, d1);
}

// Horizontal blur + SSIM for one stored row (4 cols per thread).
// rowbase = &sq[pbuf][hrow][0][0]; quantity q at rowbase + q*RB.
static __device__ __forceinline__ float hproc(const float* rowbase, int u,
                                              const u64 Wv[6], u64 C1_2, u64 C2_2,
                                              u64 EPS2, u64 NEG1, u64 TWO) {
    u64 hA[4], hB[4];
#pragma unroll
    for (int q = 0; q < 4; ++q) {
        const float4* P = reinterpret_cast<const float4*>(rowbase + q * RB) + u;
        const float4 a = P[0], bq = P[1], cq = P[2], d = P[3];
        // U_j = cols (4u-6+2j, 4u-5+2j), j=0..7
        const u64 U0 = pk2(a.x, a.y),  U1 = pk2(a.z, a.w);
        const u64 U2 = pk2(bq.x, bq.y), U3 = pk2(bq.z, bq.w);
        const u64 U4 = pk2(cq.x, cq.y), U5 = pk2(cq.z, cq.w);
        const u64 U6 = pk2(d.x, d.y),  U7 = pk2(d.z, d.w);
        const u64 A2 = add2(U2, U3), A3 = add2(U3, U4), A4 = add2(U4, U5);
        const u64 B1 = add2(U1, U4), B2 = add2(U2, U5), B3 = add2(U3, U6);
        const u64 Cg0 = add2(U0, U5), Cg1 = add2(U1, U6), Cg2 = add2(U2, U7);
        // m = 0 (cols 4u, 4u+1)
        u64 h = mul2(Wv[5], U3);
        h = fma2(Wv[3], add2(U2, U4), h);
        h = fma2(Wv[1], add2(U1, U5), h);
        h = fma2(Wv[4], hilo(A2, A3), h);
        h = fma2(Wv[2], hilo(B1, B2), h);
        h = fma2(Wv[0], hilo(Cg0, Cg1), h);
        hA[q] = h;
        // m = 1 (cols 4u+2, 4u+3)
        u64 g = mul2(Wv[5], U4);
        g = fma2(Wv[3], add2(U3, U5), g);
        g = fma2(Wv[1], add2(U2, U6), g);
        g = fma2(Wv[4], hilo(A3, A4), g);
        g = fma2(Wv[2], hilo(B2, B3), g);
        g = fma2(Wv[0], hilo(Cg1, Cg2), g);
        hB[q] = g;
    }
    return ssim2(hA, C1_2, C2_2, EPS2, NEG1, TWO)
         + ssim2(hB, C1_2, C2_2, EPS2, NEG1, TWO);
}

__global__ __launch_bounds__(NT, 2)
void ssim_main(const float* __restrict__ X, const float* __restrict__ Y,
               float* __restrict__ out) {
    // 4 phase buffers (dynamic smem): [buffer][row-in-phase][quantity][RB]
    extern __shared__ __align__(16) float sqd[];
    __shared__ float wsum[NT / 32];
    __shared__ int amLast;

#define SQROW(pb, r) (sqd + (((pb) * 2 + (r)) * 4) * RB)

    const int t = threadIdx.x;              // vertical role: cols (2t, 2t+1)
    const int b = blockIdx.x;               // 0..295

    // ---- Balanced tiling: planes 0-7 have 7 chunks, planes 8-47 have 6 ----
    int plane, r0, ch;
    if (b < 56) {
        plane = b / 7;
        const int c = b % 7;                 // sizes 74,74,74,74,72,72,72
        ch = (c < 4) ? 74 : 72;
        r0 = (c < 4) ? 74 * c : 296 + 72 * (c - 4);
    } else {
        const int bb = b - 56;
        plane = 8 + bb / 6;
        const int c = bb % 6;                // sizes 86,86,86,86,84,84
        ch = (c < 4) ? 86 : 84;
        r0 = (c < 4) ? 86 * c : 344 + 84 * (c - 4);
    }
    const int riter = ch + 10;

    const int hrow = t >> 7;                // horizontal role: row-in-phase
    const int u    = t & 127;               // horizontal role: cols 4u..4u+3

    const float2* __restrict__ X2 =
        reinterpret_cast<const float2*>(X + (size_t)plane * W * H);
    const float2* __restrict__ Y2 =
        reinterpret_cast<const float2*>(Y + (size_t)plane * W * H);

    // Zero pads once (stores below only touch idx [6 .. 517]).
    if (t < 6) {
#pragma unroll
        for (int pb = 0; pb < 4; ++pb)
#pragma unroll
            for (int r = 0; r < 2; ++r)
#pragma unroll
                for (int q = 0; q < 4; ++q) SQROW(pb, r)[q * RB + t] = 0.f;
    }
    if (t < 10) {
#pragma unroll
        for (int pb = 0; pb < 4; ++pb)
#pragma unroll
            for (int r = 0; r < 2; ++r)
#pragma unroll
                for (int q = 0; q < 4; ++q) SQROW(pb, r)[q * RB + 518 + t] = 0.f;
    }

    const float Gw[6] = {0.00102838f, 0.00759875f, 0.03600077f,
                         0.10936070f, 0.21300554f, 0.26601172f};
    u64 Wv[6];
#pragma unroll
    for (int i = 0; i < 6; ++i) Wv[i] = pk2(Gw[i], Gw[i]);
    const u64 NEG1 = pk2(-1.f, -1.f);
    const u64 TWO  = pk2(2.f, 2.f);
    const u64 C1_2 = pk2(C1c, C1c);
    const u64 C2_2 = pk2(C2c, C2c);
    const u64 EPS2 = pk2(1e-8f, 1e-8f);

    // 12-slot register ring of raw x,y (packed column pair). Row r -> slot r%12.
    u64 xr[12], yr[12];

    // Prefetch rows 0,1 (image rows r0-5, r0-4).
    float2 p0x, p0y, p1x, p1y;
    {
        const int ra = r0 - 5, rb = r0 - 4;
        const bool oa = ((unsigned)ra < (unsigned)H);
        const bool ob = ((unsigned)rb < (unsigned)H);
        p0x = oa ? X2[(size_t)ra * (W / 2) + t] : make_float2(0.f, 0.f);
        p0y = oa ? Y2[(size_t)ra * (W / 2) + t] : make_float2(0.f, 0.f);
        p1x = ob ? X2[(size_t)rb * (W / 2) + t] : make_float2(0.f, 0.f);
        p1y = ob ? Y2[(size_t)rb * (W / 2) + t] : make_float2(0.f, 0.f);
    }

    float acc = 0.f;

    // 6-phase inner unroll (12 rows = ring period). Barrier every OTHER
    // output phase; horizontal then processes the 2 pending row-pairs.
    // oidx = (rr-10)/2; parity of oidx == parity of (ph+1) (outer/2 even).
#pragma unroll 1
    for (int outer = 0; outer < MAXRI; outer += 12) {
#pragma unroll
        for (int ph = 0; ph < 6; ++ph) {
            const int rr = outer + 2 * ph;          // even; rows rr, rr+1
            if (rr < riter) {
                const int k0 = 2 * ph;              // slot of row rr
                const int k1 = 2 * ph + 1;          // slot of row rr+1

                // Slots k0,k1 hold rows rr-12, rr-11 -- needed by no vert.
                xr[k0] = pkf2(p0x); yr[k0] = pkf2(p0y);
                xr[k1] = pkf2(p1x); yr[k1] = pkf2(p1y);

                // Prefetch rows rr+2, rr+3 at phase top (full-phase overlap).
                {
                    const int ra = r0 - 5 + rr + 2, rb = ra + 1;
                    const bool oa = (rr + 2 < riter) && ((unsigned)ra < (unsigned)H);
                    const bool ob = (rr + 3 < riter) && ((unsigned)rb < (unsigned)H);
                    p0x = oa ? X2[(size_t)ra * (W / 2) + t] : make_float2(0.f, 0.f);
                    p0y = oa ? Y2[(size_t)ra * (W / 2) + t] : make_float2(0.f, 0.f);
                    p1x = ob ? X2[(size_t)rb * (W / 2) + t] : make_float2(0.f, 0.f);
                    p1y = ob ? Y2[(size_t)rb * (W / 2) + t] : make_float2(0.f, 0.f);
                }

                if (rr >= 10) {
                    const int oidx = (rr - 10) >> 1;
                    const int pbuf = oidx & 3;       // runtime addr is fine

                    // ---- Vertical blur for output rows rr-10, rr-9 ----
                    u64 v0[4], v1[4];
                    vert(xr, yr, k0, Wv, v0);
                    vert(xr, yr, k1, Wv, v1);

                    // ---- Exchange: aligned STS.64 (idx 6+2t is even) ----
                    float* s0 = SQROW(pbuf, 0) + 6 + 2 * t;
                    float* s1 = SQROW(pbuf, 1) + 6 + 2 * t;
#pragma unroll
                    for (int q = 0; q < 4; ++q) {
                        *reinterpret_cast<u64*>(s0 + q * RB) = v0[q];
                        *reinterpret_cast<u64*>(s1 + q * RB) = v1[q];
                    }

                    // Barrier + horizontal only on odd oidx (ph even):
                    // process buffers oidx-1 then oidx (row order preserved).
                    if ((ph & 1) == 0) {
                        __syncthreads();
                        const int pprev = (pbuf + 3) & 3;
                        acc += hproc(SQROW(pprev, hrow), u, Wv,
                                     C1_2, C2_2, EPS2, NEG1, TWO);
                        acc += hproc(SQROW(pbuf, hrow), u, Wv,
                                     C1_2, C2_2, EPS2, NEG1, TWO);
                    }
                }
            }
        }
    }

    // ---- Drain: if ch/2 is odd, the last buffer (even oidx) is pending ----
    if ((ch >> 1) & 1) {
        __syncthreads();
        const int pbl = ((riter - 12) >> 1) & 3;   // last oidx mod 4
        acc += hproc(SQROW(pbl, hrow), u, Wv, C1_2, C2_2, EPS2, NEG1, TWO);
    }

    // ---- Deterministic block reduction ----
#pragma unroll
    for (int off = 16; off > 0; off >>= 1)
        acc += __shfl_down_sync(0xffffffffu, acc, off);
    const int lane = t & 31, wid = t >> 5;
    if (lane == 0) wsum[wid] = acc;
    __syncthreads();
    if (wid == 0) {
        float v = (lane < NT / 32) ? wsum[lane] : 0.f;
#pragma unroll
        for (int off = 4; off > 0; off >>= 1)
            v += __shfl_down_sync(0xffffffffu, v, off);
        if (lane == 0) g_partials[b] = v;
    }

    // ---- Fused finalize: last block reduces all partials ----
    if (t == 0) {
        __threadfence();
        const int prev = atomicAdd(&g_count, 1);
        amLast = (prev == NBLK - 1);
    }
    __syncthreads();
    if (amLast) {
        float s = (t < NBLK) ? g_partials[t] : 0.f;
        if (t + 256 < NBLK) s += g_partials[t + 256];
#pragma unroll
        for (int off = 16; off > 0; off >>= 1)
            s += __shfl_down_sync(0xffffffffu, s, off);
        if (lane == 0) wsum[wid] = s;
        __syncthreads();
        if (wid == 0) {
            float v = (lane < NT / 32) ? wsum[lane] : 0.f;
#pragma unroll
            for (int off = 4; off > 0; off >>= 1)
                v += __shfl_down_sync(0xffffffffu, v, off);
            if (lane == 0) {
                constexpr float invN = 1.0f / (float)((size_t)PLANES * W * H);
                out[0] = 1.0f - v * invN;
                g_count = 0;        // reset for next graph replay
            }
        }
    }
#undef SQROW
}

extern "C" void kernel_launch(void* const* d_in, const int* in_sizes, int n_in,
                              void* d_out, int out_size) {
    const float* X = (const float*)d_in[0];
    const float* Y = (const float*)d_in[1];
    float* out = (float*)d_out;

    cudaFuncSetAttribute(ssim_main, cudaFuncAttributeMaxDynamicSharedMemorySize,
                         SMEM_BYTES);
    ssim_main<<<NBLK, NT, SMEM_BYTES>>>(X, Y, out);  // 296 blocks, occ 2
}